// round 7
// baseline (speedup 1.0000x reference)
#include <cuda_runtime.h>

// ---------------------------------------------------------------------------
// EnhancedQuanvolution: x(65536,1,28,28) -> 2x2 patches -> cumprod(cos)
// -> feat(784) @ W^T(784,10) + b -> log_softmax -> out(65536,10)
//
// Round 7: 14 warps/SM (block=448, 1 img/thread) + output-packed f32x2
// accumulators (acc[op] = {logit_2op, logit_2op+1}, 5 u64 per thread).
// Warp-private double-buffered cp.async pipeline, no block barriers in the
// main loop. Weights in smem as ws[patch][op_pair][k] = {W[2op][.],W[2op+1][.]}
// (10 broadcast LDS.128 per patch). grid=147 (one wave on 148 SMs).
// ---------------------------------------------------------------------------

__device__ __forceinline__ unsigned long long f32x2_fma(unsigned long long a,
                                                        unsigned long long b,
                                                        unsigned long long c) {
    unsigned long long d;
    asm("fma.rn.f32x2 %0, %1, %2, %3;" : "=l"(d) : "l"(a), "l"(b), "l"(c));
    return d;
}

__device__ __forceinline__ unsigned long long pack2(float lo, float hi) {
    unsigned long long d;
    asm("mov.b64 %0, {%1, %2};" : "=l"(d) : "f"(lo), "f"(hi));
    return d;
}

__device__ __forceinline__ void unpack2(unsigned long long v, float& lo, float& hi) {
    asm("mov.b64 {%0, %1}, %2;" : "=f"(lo), "=f"(hi) : "l"(v));
}

__device__ __forceinline__ void cp_async16(void* dst_smem, const void* src_gmem) {
    unsigned sd = (unsigned)__cvta_generic_to_shared(dst_smem);
    asm volatile("cp.async.cg.shared.global [%0], [%1], 16;"
                 :: "r"(sd), "l"(src_gmem) : "memory");
}

static constexpr int THREADS       = 448;   // 14 warps
static constexpr int WARPS         = 14;
static constexpr int IMG_PER_WARP  = 32;    // 1 per thread
static constexpr int IMG_PER_BLOCK = WARPS * IMG_PER_WARP;       // 448
static constexpr int NCHUNK        = 14;
static constexpr int PLANE_FLOATS  = IMG_PER_WARP * 28;          // 896 (3584B)
static constexpr int SLOT_FLOATS   = 2 * PLANE_FLOATS;           // 1792 (7168B)
static constexpr int WARP_FLOATS   = 2 * SLOT_FLOATS;            // double buffer
static constexpr int STAGE_FLOATS  = WARPS * WARP_FLOATS;        // 50176 (200704B)
static constexpr int WS_U64        = 196 * 20;                   // 3920 (31360B)
static constexpr int SMEM_BYTES    = STAGE_FLOATS * 4 + WS_U64 * 8 + 40; // 232104

// Stage chunk c (image rows 2c,2c+1) for this warp's 32 images into slotbase.
__device__ __forceinline__ void stage_chunk(const float* __restrict__ x,
                                            float* __restrict__ slotbase,
                                            int gbase, int batch,
                                            int c, int lane) {
#pragma unroll
    for (int k = 0; k < 14; k++) {
        int n = lane + 32 * k;           // 0..447 = 32 imgs * 14 float4
        int img = n / 14;
        int j = n - img * 14;            // float4 index within 224B chunk
        int gimg = gbase + img;
        if (gimg < batch) {
            const float* src = x + (size_t)gimg * 784 + c * 56 + j * 4;
            float* dst = slotbase + ((j < 7) ? 0 : PLANE_FLOATS) + img * 28
                       + ((j < 7) ? j : (j - 7)) * 4;
            cp_async16(dst, src);
        }
    }
    asm volatile("cp.async.commit_group;" ::: "memory");
}

// cumprod-of-cos feature, duplicated into f32x2 lanes: dup[k] = {f_k, f_k}
__device__ __forceinline__ void patch_feat_dup(float a, float b, float c, float d,
                                               unsigned long long* dup) {
    float f0 = __cosf(a);
    float f1 = f0 * __cosf(b);
    float f2 = f1 * __cosf(c);
    float f3 = f2 * __cosf(d);
    dup[0] = pack2(f0, f0);
    dup[1] = pack2(f1, f1);
    dup[2] = pack2(f2, f2);
    dup[3] = pack2(f3, f3);
}

__global__ __launch_bounds__(THREADS, 1)
void quanv_kernel(const float* __restrict__ x,
                  const float* __restrict__ W,
                  const float* __restrict__ bias,
                  float* __restrict__ out,
                  int batch) {
    extern __shared__ float sm[];
    unsigned long long* ws = (unsigned long long*)(sm + STAGE_FLOATS);
    float* bsh = (float*)(ws + WS_U64);

    const int tid  = threadIdx.x;
    const int lane = tid & 31;
    const int warp = tid >> 5;

    // ---- pack weights: ws[p*20 + op*4 + k] = {W[2op][4p+k], W[2op+1][4p+k]} --
    for (int n = tid; n < WS_U64; n += THREADS) {
        int patch = n / 20;
        int t = n % 20;
        int op = t >> 2;          // output pair 0..4
        int k = t & 3;            // feature index within patch
        int f = patch * 4 + k;
        ws[n] = pack2(W[(2 * op) * 784 + f], W[(2 * op + 1) * 784 + f]);
    }
    if (tid < 10) bsh[tid] = bias[tid];
    __syncthreads();   // only block-wide barrier

    const int gbase = blockIdx.x * IMG_PER_BLOCK + warp * IMG_PER_WARP;
    float* wbuf = sm + warp * WARP_FLOATS;
    const int img = gbase + lane;
    const bool ok = img < batch;

    // ---- prologue: stage chunks 0,1 ------------------------------------------
    stage_chunk(x, wbuf, gbase, batch, 0, lane);
    stage_chunk(x, wbuf + SLOT_FLOATS, gbase, batch, 1, lane);

    unsigned long long acc[5];
#pragma unroll
    for (int op = 0; op < 5; op++) acc[op] = 0ULL;

#pragma unroll 1
    for (int c = 0; c < NCHUNK; c++) {
        if (c < NCHUNK - 1) asm volatile("cp.async.wait_group 1;" ::: "memory");
        else                asm volatile("cp.async.wait_group 0;" ::: "memory");
        __syncwarp();

        float* slot = wbuf + (c & 1) * SLOT_FLOATS;
        const float4* p0 = (const float4*)(slot + lane * 28);                // row 2c
        const float4* p1 = (const float4*)(slot + PLANE_FLOATS + lane * 28); // row 2c+1

#pragma unroll 1
        for (int v = 0; v < 7; v++) {
            float4 q0 = p0[v];
            float4 q1 = p1[v];
            const ulonglong2* wp = (const ulonglong2*)&ws[(c * 14 + 2 * v) * 20];

            // ---- patch (c, 2v): x/y halves ----
            {
                unsigned long long d[4];
                patch_feat_dup(q0.x, q0.y, q1.x, q1.y, d);
#pragma unroll
                for (int op = 0; op < 5; op++) {
                    ulonglong2 w01 = wp[op * 2];       // k0,k1
                    ulonglong2 w23 = wp[op * 2 + 1];   // k2,k3
                    acc[op] = f32x2_fma(d[0], w01.x, acc[op]);
                    acc[op] = f32x2_fma(d[1], w01.y, acc[op]);
                    acc[op] = f32x2_fma(d[2], w23.x, acc[op]);
                    acc[op] = f32x2_fma(d[3], w23.y, acc[op]);
                }
            }
            // ---- patch (c, 2v+1): z/w halves ----
            {
                unsigned long long d[4];
                patch_feat_dup(q0.z, q0.w, q1.z, q1.w, d);
                const ulonglong2* wq = wp + 10;        // next patch's 20 u64
#pragma unroll
                for (int op = 0; op < 5; op++) {
                    ulonglong2 w01 = wq[op * 2];
                    ulonglong2 w23 = wq[op * 2 + 1];
                    acc[op] = f32x2_fma(d[0], w01.x, acc[op]);
                    acc[op] = f32x2_fma(d[1], w01.y, acc[op]);
                    acc[op] = f32x2_fma(d[2], w23.x, acc[op]);
                    acc[op] = f32x2_fma(d[3], w23.y, acc[op]);
                }
            }
        }
        __syncwarp();

        if (c + 2 < NCHUNK) stage_chunk(x, slot, gbase, batch, c + 2, lane);
    }

    if (!ok) return;

    // ---- logits + log_softmax ---------------------------------------------------
    float lg[10];
    float m = -1e30f;
#pragma unroll
    for (int op = 0; op < 5; op++) {
        float lo, hi;
        unpack2(acc[op], lo, hi);
        lg[2 * op]     = lo + bsh[2 * op];
        lg[2 * op + 1] = hi + bsh[2 * op + 1];
        m = fmaxf(m, fmaxf(lg[2 * op], lg[2 * op + 1]));
    }
    float s = 0.f;
#pragma unroll
    for (int o = 0; o < 10; o++) s += __expf(lg[o] - m);
    float lse = m + __logf(s);

    float* op_ = out + (size_t)img * 10;
#pragma unroll
    for (int o = 0; o < 10; o += 2) {
        *(float2*)(op_ + o) = make_float2(lg[o] - lse, lg[o + 1] - lse);
    }
}

extern "C" void kernel_launch(void* const* d_in, const int* in_sizes, int n_in,
                              void* d_out, int out_size) {
    const float* x = (const float*)d_in[0];   // (B,1,28,28) fp32
    const float* W = (const float*)d_in[1];   // (10,784)    fp32
    const float* b = (const float*)d_in[2];   // (10,)       fp32
    float* out = (float*)d_out;               // (B,10)      fp32

    int batch = in_sizes[0] / 784;
    int grid = (batch + IMG_PER_BLOCK - 1) / IMG_PER_BLOCK;

    cudaFuncSetAttribute(quanv_kernel,
                         cudaFuncAttributeMaxDynamicSharedMemorySize, SMEM_BYTES);
    quanv_kernel<<<grid, THREADS, SMEM_BYTES>>>(x, W, b, out, batch);
}

// round 8
// speedup vs baseline: 1.0035x; 1.0035x over previous
#include <cuda_runtime.h>

// ---------------------------------------------------------------------------
// EnhancedQuanvolution: x(65536,1,28,28) -> 2x2 patches -> cumprod(cos)
// -> feat(784) @ W^T(784,10) + b -> log_softmax -> out(65536,10)
//
// Round 7: 14 warps/SM (block=448, 1 img/thread) + output-packed f32x2
// accumulators (acc[op] = {logit_2op, logit_2op+1}, 5 u64 per thread).
// Warp-private double-buffered cp.async pipeline, no block barriers in the
// main loop. Weights in smem as ws[patch][op_pair][k] = {W[2op][.],W[2op+1][.]}
// (10 broadcast LDS.128 per patch). grid=147 (one wave on 148 SMs).
// ---------------------------------------------------------------------------

__device__ __forceinline__ unsigned long long f32x2_fma(unsigned long long a,
                                                        unsigned long long b,
                                                        unsigned long long c) {
    unsigned long long d;
    asm("fma.rn.f32x2 %0, %1, %2, %3;" : "=l"(d) : "l"(a), "l"(b), "l"(c));
    return d;
}

__device__ __forceinline__ unsigned long long pack2(float lo, float hi) {
    unsigned long long d;
    asm("mov.b64 %0, {%1, %2};" : "=l"(d) : "f"(lo), "f"(hi));
    return d;
}

__device__ __forceinline__ void unpack2(unsigned long long v, float& lo, float& hi) {
    asm("mov.b64 {%0, %1}, %2;" : "=f"(lo), "=f"(hi) : "l"(v));
}

__device__ __forceinline__ void cp_async16(void* dst_smem, const void* src_gmem) {
    unsigned sd = (unsigned)__cvta_generic_to_shared(dst_smem);
    asm volatile("cp.async.cg.shared.global [%0], [%1], 16;"
                 :: "r"(sd), "l"(src_gmem) : "memory");
}

static constexpr int THREADS       = 448;   // 14 warps
static constexpr int WARPS         = 14;
static constexpr int IMG_PER_WARP  = 32;    // 1 per thread
static constexpr int IMG_PER_BLOCK = WARPS * IMG_PER_WARP;       // 448
static constexpr int NCHUNK        = 14;
static constexpr int PLANE_FLOATS  = IMG_PER_WARP * 28;          // 896 (3584B)
static constexpr int SLOT_FLOATS   = 2 * PLANE_FLOATS;           // 1792 (7168B)
static constexpr int WARP_FLOATS   = 2 * SLOT_FLOATS;            // double buffer
static constexpr int STAGE_FLOATS  = WARPS * WARP_FLOATS;        // 50176 (200704B)
static constexpr int WS_U64        = 196 * 20;                   // 3920 (31360B)
static constexpr int SMEM_BYTES    = STAGE_FLOATS * 4 + WS_U64 * 8 + 40; // 232104

// Stage chunk c (image rows 2c,2c+1) for this warp's 32 images into slotbase.
__device__ __forceinline__ void stage_chunk(const float* __restrict__ x,
                                            float* __restrict__ slotbase,
                                            int gbase, int batch,
                                            int c, int lane) {
#pragma unroll
    for (int k = 0; k < 14; k++) {
        int n = lane + 32 * k;           // 0..447 = 32 imgs * 14 float4
        int img = n / 14;
        int j = n - img * 14;            // float4 index within 224B chunk
        int gimg = gbase + img;
        if (gimg < batch) {
            const float* src = x + (size_t)gimg * 784 + c * 56 + j * 4;
            float* dst = slotbase + ((j < 7) ? 0 : PLANE_FLOATS) + img * 28
                       + ((j < 7) ? j : (j - 7)) * 4;
            cp_async16(dst, src);
        }
    }
    asm volatile("cp.async.commit_group;" ::: "memory");
}

// cumprod-of-cos feature, duplicated into f32x2 lanes: dup[k] = {f_k, f_k}
__device__ __forceinline__ void patch_feat_dup(float a, float b, float c, float d,
                                               unsigned long long* dup) {
    float f0 = __cosf(a);
    float f1 = f0 * __cosf(b);
    float f2 = f1 * __cosf(c);
    float f3 = f2 * __cosf(d);
    dup[0] = pack2(f0, f0);
    dup[1] = pack2(f1, f1);
    dup[2] = pack2(f2, f2);
    dup[3] = pack2(f3, f3);
}

__global__ __launch_bounds__(THREADS, 1)
void quanv_kernel(const float* __restrict__ x,
                  const float* __restrict__ W,
                  const float* __restrict__ bias,
                  float* __restrict__ out,
                  int batch) {
    extern __shared__ float sm[];
    unsigned long long* ws = (unsigned long long*)(sm + STAGE_FLOATS);
    float* bsh = (float*)(ws + WS_U64);

    const int tid  = threadIdx.x;
    const int lane = tid & 31;
    const int warp = tid >> 5;

    // ---- pack weights: ws[p*20 + op*4 + k] = {W[2op][4p+k], W[2op+1][4p+k]} --
    for (int n = tid; n < WS_U64; n += THREADS) {
        int patch = n / 20;
        int t = n % 20;
        int op = t >> 2;          // output pair 0..4
        int k = t & 3;            // feature index within patch
        int f = patch * 4 + k;
        ws[n] = pack2(W[(2 * op) * 784 + f], W[(2 * op + 1) * 784 + f]);
    }
    if (tid < 10) bsh[tid] = bias[tid];
    __syncthreads();   // only block-wide barrier

    const int gbase = blockIdx.x * IMG_PER_BLOCK + warp * IMG_PER_WARP;
    float* wbuf = sm + warp * WARP_FLOATS;
    const int img = gbase + lane;
    const bool ok = img < batch;

    // ---- prologue: stage chunks 0,1 ------------------------------------------
    stage_chunk(x, wbuf, gbase, batch, 0, lane);
    stage_chunk(x, wbuf + SLOT_FLOATS, gbase, batch, 1, lane);

    unsigned long long acc[5];
#pragma unroll
    for (int op = 0; op < 5; op++) acc[op] = 0ULL;

#pragma unroll 1
    for (int c = 0; c < NCHUNK; c++) {
        if (c < NCHUNK - 1) asm volatile("cp.async.wait_group 1;" ::: "memory");
        else                asm volatile("cp.async.wait_group 0;" ::: "memory");
        __syncwarp();

        float* slot = wbuf + (c & 1) * SLOT_FLOATS;
        const float4* p0 = (const float4*)(slot + lane * 28);                // row 2c
        const float4* p1 = (const float4*)(slot + PLANE_FLOATS + lane * 28); // row 2c+1

#pragma unroll 1
        for (int v = 0; v < 7; v++) {
            float4 q0 = p0[v];
            float4 q1 = p1[v];
            const ulonglong2* wp = (const ulonglong2*)&ws[(c * 14 + 2 * v) * 20];

            // ---- patch (c, 2v): x/y halves ----
            {
                unsigned long long d[4];
                patch_feat_dup(q0.x, q0.y, q1.x, q1.y, d);
#pragma unroll
                for (int op = 0; op < 5; op++) {
                    ulonglong2 w01 = wp[op * 2];       // k0,k1
                    ulonglong2 w23 = wp[op * 2 + 1];   // k2,k3
                    acc[op] = f32x2_fma(d[0], w01.x, acc[op]);
                    acc[op] = f32x2_fma(d[1], w01.y, acc[op]);
                    acc[op] = f32x2_fma(d[2], w23.x, acc[op]);
                    acc[op] = f32x2_fma(d[3], w23.y, acc[op]);
                }
            }
            // ---- patch (c, 2v+1): z/w halves ----
            {
                unsigned long long d[4];
                patch_feat_dup(q0.z, q0.w, q1.z, q1.w, d);
                const ulonglong2* wq = wp + 10;        // next patch's 20 u64
#pragma unroll
                for (int op = 0; op < 5; op++) {
                    ulonglong2 w01 = wq[op * 2];
                    ulonglong2 w23 = wq[op * 2 + 1];
                    acc[op] = f32x2_fma(d[0], w01.x, acc[op]);
                    acc[op] = f32x2_fma(d[1], w01.y, acc[op]);
                    acc[op] = f32x2_fma(d[2], w23.x, acc[op]);
                    acc[op] = f32x2_fma(d[3], w23.y, acc[op]);
                }
            }
        }
        __syncwarp();

        if (c + 2 < NCHUNK) stage_chunk(x, slot, gbase, batch, c + 2, lane);
    }

    if (!ok) return;

    // ---- logits + log_softmax ---------------------------------------------------
    float lg[10];
    float m = -1e30f;
#pragma unroll
    for (int op = 0; op < 5; op++) {
        float lo, hi;
        unpack2(acc[op], lo, hi);
        lg[2 * op]     = lo + bsh[2 * op];
        lg[2 * op + 1] = hi + bsh[2 * op + 1];
        m = fmaxf(m, fmaxf(lg[2 * op], lg[2 * op + 1]));
    }
    float s = 0.f;
#pragma unroll
    for (int o = 0; o < 10; o++) s += __expf(lg[o] - m);
    float lse = m + __logf(s);

    float* op_ = out + (size_t)img * 10;
#pragma unroll
    for (int o = 0; o < 10; o += 2) {
        *(float2*)(op_ + o) = make_float2(lg[o] - lse, lg[o + 1] - lse);
    }
}

extern "C" void kernel_launch(void* const* d_in, const int* in_sizes, int n_in,
                              void* d_out, int out_size) {
    const float* x = (const float*)d_in[0];   // (B,1,28,28) fp32
    const float* W = (const float*)d_in[1];   // (10,784)    fp32
    const float* b = (const float*)d_in[2];   // (10,)       fp32
    float* out = (float*)d_out;               // (B,10)      fp32

    int batch = in_sizes[0] / 784;
    int grid = (batch + IMG_PER_BLOCK - 1) / IMG_PER_BLOCK;

    cudaFuncSetAttribute(quanv_kernel,
                         cudaFuncAttributeMaxDynamicSharedMemorySize, SMEM_BYTES);
    quanv_kernel<<<grid, THREADS, SMEM_BYTES>>>(x, W, b, out, batch);
}

// round 10
// speedup vs baseline: 1.1946x; 1.1905x over previous
#include <cuda_runtime.h>
#include <cuda_bf16.h>

// ---------------------------------------------------------------------------
// EnhancedQuanvolution via warp-level HMMA (mma.sync m16n8k16 bf16, base
// sm_103 legal). Each warp: 32 images. Per chunk (2 image rows, K=56 pad 64):
// coalesced LDG pixels -> cos cumprod feats -> bf16 hi/lo split -> STS to
// per-warp feat buffer -> ldmatrix A frags + LDS B frags -> 48 HMMA into
// fp32 register accumulators (3 products: AhWh + AhWl + AlWh).
// W pre-split/padded by prep kernel. Epilogue: shfl log_softmax.
// block=448 (14 warps), grid=147.
// ---------------------------------------------------------------------------

static constexpr int THREADS   = 448;
static constexpr int WARPS     = 14;
static constexpr int IMG_BLK   = 448;
static constexpr int NCHUNK    = 14;
static constexpr int FROW      = 144;              // 64 k * 2B + 16B pad (bank rotate)
static constexpr int FBUF      = 32 * FROW;        // 4608 B (hi or lo, per warp)
static constexpr int WCHUNK    = 2 * 16 * FROW;    // 4608 B per chunk (hi16 + lo16 rows)
static constexpr int OFF_FEAT  = NCHUNK * WCHUNK;  // 64512
static constexpr int OFF_BIAS  = OFF_FEAT + WARPS * 2 * FBUF;  // 193536
static constexpr int SMEM_REQ  = OFF_BIAS + 64;

__device__ __align__(16) unsigned char gWp[NCHUNK * WCHUNK];

// Split W into bf16 hi (RZ trunc) + lo (RN residual), zero-padded (n>=10, k>=56).
__global__ void prep_w(const float* __restrict__ W) {
    int i = blockIdx.x * blockDim.x + threadIdx.x;   // 14*16*64 = 14336
    if (i >= NCHUNK * 16 * 64) return;
    int c = i >> 10, n = (i >> 6) & 15, k = i & 63;
    float w = (n < 10 && k < 56) ? W[n * 784 + c * 56 + k] : 0.f;
    unsigned u = __float_as_uint(w);
    float lo = w - __uint_as_float(u & 0xffff0000u);
    unsigned char* base = gWp + c * WCHUNK;
    *(unsigned short*)(base + n * FROW + k * 2) = (unsigned short)(u >> 16);
    *(unsigned short*)(base + 16 * FROW + n * FROW + k * 2) =
        __bfloat16_as_ushort(__float2bfloat16(lo));
}

__device__ __forceinline__ void cp_async16(unsigned dst, const void* src) {
    asm volatile("cp.async.cg.shared.global [%0], [%1], 16;" :: "r"(dst), "l"(src) : "memory");
}
__device__ __forceinline__ unsigned lds32(unsigned a) {
    unsigned v; asm volatile("ld.shared.b32 %0, [%1];" : "=r"(v) : "r"(a)); return v;
}
__device__ __forceinline__ void sts128(unsigned a, unsigned r0, unsigned r1,
                                       unsigned r2, unsigned r3) {
    asm volatile("st.shared.v4.b32 [%0], {%1,%2,%3,%4};"
                 :: "r"(a), "r"(r0), "r"(r1), "r"(r2), "r"(r3) : "memory");
}
__device__ __forceinline__ void ldsm4(unsigned* r, unsigned a) {
    asm volatile("ldmatrix.sync.aligned.m8n8.x4.shared.b16 {%0,%1,%2,%3}, [%4];"
                 : "=r"(r[0]), "=r"(r[1]), "=r"(r[2]), "=r"(r[3]) : "r"(a));
}
__device__ __forceinline__ void mma16816(float* d, const unsigned* a,
                                         unsigned b0, unsigned b1) {
    asm volatile("mma.sync.aligned.m16n8k16.row.col.f32.bf16.bf16.f32 "
                 "{%0,%1,%2,%3}, {%4,%5,%6,%7}, {%8,%9}, {%0,%1,%2,%3};"
                 : "+f"(d[0]), "+f"(d[1]), "+f"(d[2]), "+f"(d[3])
                 : "r"(a[0]), "r"(a[1]), "r"(a[2]), "r"(a[3]), "r"(b0), "r"(b1));
}
// pack 2 floats -> bf16x2 hi (RZ trunc) + lo (RN residual)
__device__ __forceinline__ void split2(float a, float b, unsigned& h, unsigned& l) {
    unsigned ua = __float_as_uint(a), ub = __float_as_uint(b);
    asm("prmt.b32 %0, %1, %2, 0x7632;" : "=r"(h) : "r"(ua), "r"(ub));
    float la = a - __uint_as_float(ua & 0xffff0000u);
    float lb = b - __uint_as_float(ub & 0xffff0000u);
    asm("cvt.rn.bf16x2.f32 %0, %1, %2;" : "=r"(l) : "f"(lb), "f"(la));
}

__global__ __launch_bounds__(THREADS, 1)
void quanv_hmma(const float* __restrict__ x, const float* __restrict__ bias,
                float* __restrict__ out, int batch) {
    extern __shared__ unsigned char sm[];
    const unsigned smb = (unsigned)__cvta_generic_to_shared(sm);
    float* bias_sh = (float*)(sm + OFF_BIAS);

    const int tid = threadIdx.x, lane = tid & 31, wid = tid >> 5;

    // ---- init: copy pre-split W (cp.async), zero feat buffers, bias --------
#pragma unroll
    for (int r = 0; r < 9; r++) {                 // 9*448*16 = 64512
        int off = (tid + r * THREADS) * 16;
        cp_async16(smb + off, gWp + off);
    }
    asm volatile("cp.async.commit_group;" ::: "memory");
    float4 z4 = make_float4(0.f, 0.f, 0.f, 0.f);
#pragma unroll
    for (int r = 0; r < 18; r++) {                // 18*448*16 = 129024
        int off = OFF_FEAT + (tid + r * THREADS) * 16;
        *(float4*)(sm + off) = z4;
    }
    if (tid < 10) bias_sh[tid] = bias[tid];
    asm volatile("cp.async.wait_group 0;" ::: "memory");
    __syncthreads();

    const int wimg = blockIdx.x * IMG_BLK + wid * 32;       // warp's first image
    const unsigned fhi = smb + OFF_FEAT + wid * (2 * FBUF); // per-warp feat bufs
    const unsigned flo = fhi + FBUF;

    float d[2][2][4];
#pragma unroll
    for (int m = 0; m < 2; m++)
#pragma unroll
        for (int nt = 0; nt < 2; nt++)
#pragma unroll
            for (int e = 0; e < 4; e++) d[m][nt][e] = 0.f;

#pragma unroll 1
    for (int c = 0; c < NCHUNK; c++) {
        __syncwarp();
        // ---- feats: lane handles 7 (img, col4) positions ---------------------
#pragma unroll
        for (int t = 0; t < 7; t++) {
            int n = lane + 32 * t;               // 0..223 = 32 imgs * 7 float4-cols
            int img = n / 7;
            int j = n - img * 7;                 // float4 col 0..6
            float4 q0 = z4, q1 = z4;
            if (wimg + img < batch) {
                const float* px = x + (size_t)(wimg + img) * 784 + c * 56 + j * 4;
                q0 = *(const float4*)px;          // row 2c
                q1 = *(const float4*)(px + 28);   // row 2c+1
            }
            // patch col 2j: q0.x q0.y / q1.x q1.y ; patch col 2j+1: z w / z w
            float f0 = __cosf(q0.x), f1 = f0 * __cosf(q0.y);
            float f2 = f1 * __cosf(q1.x), f3 = f2 * __cosf(q1.y);
            float g0 = __cosf(q0.z), g1 = g0 * __cosf(q0.w);
            float g2 = g1 * __cosf(q1.z), g3 = g2 * __cosf(q1.w);
            unsigned h0, h1, h2, h3, l0, l1, l2, l3;
            split2(f0, f1, h0, l0); split2(f2, f3, h1, l1);
            split2(g0, g1, h2, l2); split2(g2, g3, h3, l3);
            unsigned sa = fhi + img * FROW + j * 16;   // k = 8j..8j+7
            sts128(sa, h0, h1, h2, h3);
            sts128(sa + FBUF, l0, l1, l2, l3);
        }
        __syncwarp();

        // ---- B fragments for this chunk (shared across both M tiles) --------
        const unsigned wb = smb + c * WCHUNK;
        unsigned bh[2][4][2], bl[2][4][2];
#pragma unroll
        for (int nt = 0; nt < 2; nt++)
#pragma unroll
            for (int T = 0; T < 4; T++) {
                unsigned ba = wb + (nt * 8 + (lane >> 2)) * FROW + T * 32 + (lane & 3) * 4;
                bh[nt][T][0] = lds32(ba);
                bh[nt][T][1] = lds32(ba + 16);
                bl[nt][T][0] = lds32(ba + 16 * FROW);
                bl[nt][T][1] = lds32(ba + 16 * FROW + 16);
            }

        // ---- A fragments + MMA ----------------------------------------------
        const unsigned rowsel = (lane & 7) + 8 * ((lane >> 3) & 1);
        const unsigned koff = ((lane >> 4) & 1) * 16;
#pragma unroll
        for (int m = 0; m < 2; m++) {
            unsigned ah[4][4], al[4][4];
#pragma unroll
            for (int T = 0; T < 4; T++) {
                unsigned aa = fhi + (16 * m + rowsel) * FROW + T * 32 + koff;
                ldsm4(ah[T], aa);
                ldsm4(al[T], aa + FBUF);
            }
#pragma unroll
            for (int nt = 0; nt < 2; nt++)
#pragma unroll
                for (int T = 0; T < 4; T++) {
                    mma16816(d[m][nt], ah[T], bh[nt][T][0], bh[nt][T][1]);
                    mma16816(d[m][nt], ah[T], bl[nt][T][0], bl[nt][T][1]);
                    mma16816(d[m][nt], al[T], bh[nt][T][0], bh[nt][T][1]);
                }
        }
    }

    // ---- epilogue: bias + log_softmax (4-lane groups per image) -------------
    const int q = lane & 3;
    const float b0 = bias_sh[2 * q], b1 = bias_sh[2 * q + 1];
    const float b8 = bias_sh[8], b9 = bias_sh[9];
#pragma unroll
    for (int m = 0; m < 2; m++)
#pragma unroll
        for (int h = 0; h < 2; h++) {
            int img = wimg + 16 * m + 8 * h + (lane >> 2);
            float v0 = d[m][0][2 * h] + b0;
            float v1 = d[m][0][2 * h + 1] + b1;
            float v2 = (q == 0) ? d[m][1][2 * h] + b8 : -1e30f;
            float v3 = (q == 0) ? d[m][1][2 * h + 1] + b9 : -1e30f;
            float mx = fmaxf(fmaxf(v0, v1), fmaxf(v2, v3));
            mx = fmaxf(mx, __shfl_xor_sync(0xffffffffu, mx, 1));
            mx = fmaxf(mx, __shfl_xor_sync(0xffffffffu, mx, 2));
            float s = __expf(v0 - mx) + __expf(v1 - mx);
            if (q == 0) s += __expf(v2 - mx) + __expf(v3 - mx);
            s += __shfl_xor_sync(0xffffffffu, s, 1);
            s += __shfl_xor_sync(0xffffffffu, s, 2);
            float lse = mx + __logf(s);
            if (img < batch) {
                float* op = out + (size_t)img * 10;
                *(float2*)(op + 2 * q) = make_float2(v0 - lse, v1 - lse);
                if (q == 0) *(float2*)(op + 8) = make_float2(v2 - lse, v3 - lse);
            }
        }
}

extern "C" void kernel_launch(void* const* d_in, const int* in_sizes, int n_in,
                              void* d_out, int out_size) {
    const float* x = (const float*)d_in[0];   // (B,1,28,28) fp32
    const float* W = (const float*)d_in[1];   // (10,784)    fp32
    const float* b = (const float*)d_in[2];   // (10,)       fp32
    float* out = (float*)d_out;               // (B,10)      fp32

    int batch = in_sizes[0] / 784;

    prep_w<<<(NCHUNK * 16 * 64 + 255) / 256, 256>>>(W);

    int grid = (batch + IMG_BLK - 1) / IMG_BLK;
    cudaFuncSetAttribute(quanv_hmma, cudaFuncAttributeMaxDynamicSharedMemorySize, SMEM_REQ);
    quanv_hmma<<<grid, THREADS, SMEM_REQ>>>(x, b, out, batch);
}

// round 11
// speedup vs baseline: 1.4094x; 1.1798x over previous
#include <cuda_runtime.h>
#include <cuda_fp16.h>

// ---------------------------------------------------------------------------
// EnhancedQuanvolution via warp-level HMMA, fp16 A (single), fp16 hi/lo W
// (2 products: A*Wh + A*Wl). Each warp: 32 images; per chunk (2 image rows,
// K=56 pad 64): coalesced LDG -> cos cumprod feats -> fp16 -> STS -> ldmatrix
// A frags + LDS B frags -> 32 HMMA (m16n8k16 f16->f32).
// W pre-split/padded by prep kernel. Epilogue: shfl log_softmax.
// block=448 (14 warps), grid=147.
// ---------------------------------------------------------------------------

static constexpr int THREADS   = 448;
static constexpr int WARPS     = 14;
static constexpr int IMG_BLK   = 448;
static constexpr int NCHUNK    = 14;
static constexpr int FROW      = 144;              // 64 k * 2B + 16B pad (bank rotate)
static constexpr int FBUF      = 32 * FROW;        // 4608 B per warp (fp16 feats)
static constexpr int WCHUNK    = 2 * 16 * FROW;    // 4608 B per chunk (hi16 + lo16 rows)
static constexpr int OFF_FEAT  = NCHUNK * WCHUNK;  // 64512
static constexpr int OFF_BIAS  = OFF_FEAT + WARPS * FBUF;  // 129024
static constexpr int SMEM_REQ  = OFF_BIAS + 64;

__device__ __align__(16) unsigned char gWp[NCHUNK * WCHUNK];

// Split W into fp16 hi (RN) + fp16 lo (RN of residual), zero-pad n>=10, k>=56.
__global__ void prep_w(const float* __restrict__ W) {
    int i = blockIdx.x * blockDim.x + threadIdx.x;   // 14*16*64 = 14336
    if (i >= NCHUNK * 16 * 64) return;
    int c = i >> 10, n = (i >> 6) & 15, k = i & 63;
    float w = (n < 10 && k < 56) ? W[n * 784 + c * 56 + k] : 0.f;
    __half h = __float2half_rn(w);
    __half l = __float2half_rn(w - __half2float(h));
    unsigned char* base = gWp + c * WCHUNK;
    *(__half*)(base + n * FROW + k * 2) = h;
    *(__half*)(base + 16 * FROW + n * FROW + k * 2) = l;
}

__device__ __forceinline__ void cp_async16(unsigned dst, const void* src) {
    asm volatile("cp.async.cg.shared.global [%0], [%1], 16;" :: "r"(dst), "l"(src) : "memory");
}
__device__ __forceinline__ unsigned lds32(unsigned a) {
    unsigned v; asm volatile("ld.shared.b32 %0, [%1];" : "=r"(v) : "r"(a)); return v;
}
__device__ __forceinline__ void sts128(unsigned a, unsigned r0, unsigned r1,
                                       unsigned r2, unsigned r3) {
    asm volatile("st.shared.v4.b32 [%0], {%1,%2,%3,%4};"
                 :: "r"(a), "r"(r0), "r"(r1), "r"(r2), "r"(r3) : "memory");
}
__device__ __forceinline__ void ldsm4(unsigned* r, unsigned a) {
    asm volatile("ldmatrix.sync.aligned.m8n8.x4.shared.b16 {%0,%1,%2,%3}, [%4];"
                 : "=r"(r[0]), "=r"(r[1]), "=r"(r[2]), "=r"(r[3]) : "r"(a));
}
__device__ __forceinline__ void mma16816(float* d, const unsigned* a,
                                         unsigned b0, unsigned b1) {
    asm volatile("mma.sync.aligned.m16n8k16.row.col.f32.f16.f16.f32 "
                 "{%0,%1,%2,%3}, {%4,%5,%6,%7}, {%8,%9}, {%0,%1,%2,%3};"
                 : "+f"(d[0]), "+f"(d[1]), "+f"(d[2]), "+f"(d[3])
                 : "r"(a[0]), "r"(a[1]), "r"(a[2]), "r"(a[3]), "r"(b0), "r"(b1));
}
// pack 2 floats -> f16x2 {lo=a, hi=b}
__device__ __forceinline__ unsigned pack_h2(float a, float b) {
    unsigned r;
    asm("cvt.rn.f16x2.f32 %0, %1, %2;" : "=r"(r) : "f"(b), "f"(a));
    return r;
}

__global__ __launch_bounds__(THREADS, 1)
void quanv_hmma(const float* __restrict__ x, const float* __restrict__ bias,
                float* __restrict__ out, int batch) {
    extern __shared__ unsigned char sm[];
    const unsigned smb = (unsigned)__cvta_generic_to_shared(sm);
    float* bias_sh = (float*)(sm + OFF_BIAS);

    const int tid = threadIdx.x, lane = tid & 31, wid = tid >> 5;

    // ---- init: copy pre-split W (cp.async), zero feat buffers, bias --------
#pragma unroll
    for (int r = 0; r < 9; r++) {                 // 9*448*16 = 64512
        int off = (tid + r * THREADS) * 16;
        cp_async16(smb + off, gWp + off);
    }
    asm volatile("cp.async.commit_group;" ::: "memory");
    float4 z4 = make_float4(0.f, 0.f, 0.f, 0.f);
#pragma unroll
    for (int r = 0; r < 9; r++) {                 // 9*448*16 = 64512
        int off = OFF_FEAT + (tid + r * THREADS) * 16;
        *(float4*)(sm + off) = z4;
    }
    if (tid < 10) bias_sh[tid] = bias[tid];
    asm volatile("cp.async.wait_group 0;" ::: "memory");
    __syncthreads();

    const int wimg = blockIdx.x * IMG_BLK + wid * 32;       // warp's first image
    const unsigned fbuf = smb + OFF_FEAT + wid * FBUF;      // per-warp feat buffer

    float d[2][2][4];
#pragma unroll
    for (int m = 0; m < 2; m++)
#pragma unroll
        for (int nt = 0; nt < 2; nt++)
#pragma unroll
            for (int e = 0; e < 4; e++) d[m][nt][e] = 0.f;

#pragma unroll 1
    for (int c = 0; c < NCHUNK; c++) {
        __syncwarp();
        // ---- feats: lane handles 7 (img, col4) positions ---------------------
#pragma unroll
        for (int t = 0; t < 7; t++) {
            int n = lane + 32 * t;               // 0..223 = 32 imgs * 7 float4-cols
            int img = n / 7;
            int j = n - img * 7;                 // float4 col 0..6
            float4 q0 = z4, q1 = z4;
            if (wimg + img < batch) {
                const float* px = x + (size_t)(wimg + img) * 784 + c * 56 + j * 4;
                q0 = *(const float4*)px;          // row 2c
                q1 = *(const float4*)(px + 28);   // row 2c+1
            }
            float f0 = __cosf(q0.x), f1 = f0 * __cosf(q0.y);
            float f2 = f1 * __cosf(q1.x), f3 = f2 * __cosf(q1.y);
            float g0 = __cosf(q0.z), g1 = g0 * __cosf(q0.w);
            float g2 = g1 * __cosf(q1.z), g3 = g2 * __cosf(q1.w);
            unsigned sa = fbuf + img * FROW + j * 16;   // k = 8j..8j+7
            sts128(sa, pack_h2(f0, f1), pack_h2(f2, f3),
                       pack_h2(g0, g1), pack_h2(g2, g3));
        }
        __syncwarp();

        // ---- B fragments (hi, lo W tiles) ------------------------------------
        const unsigned wb = smb + c * WCHUNK;
        unsigned bh[2][4][2], bl[2][4][2];
#pragma unroll
        for (int nt = 0; nt < 2; nt++)
#pragma unroll
            for (int T = 0; T < 4; T++) {
                unsigned ba = wb + (nt * 8 + (lane >> 2)) * FROW + T * 32 + (lane & 3) * 4;
                bh[nt][T][0] = lds32(ba);
                bh[nt][T][1] = lds32(ba + 16);
                bl[nt][T][0] = lds32(ba + 16 * FROW);
                bl[nt][T][1] = lds32(ba + 16 * FROW + 16);
            }

        // ---- A fragments + MMA ------------------------------------------------
        const unsigned rowsel = (lane & 7) + 8 * ((lane >> 3) & 1);
        const unsigned koff = ((lane >> 4) & 1) * 16;
#pragma unroll
        for (int m = 0; m < 2; m++) {
            unsigned ah[4][4];
#pragma unroll
            for (int T = 0; T < 4; T++)
                ldsm4(ah[T], fbuf + (16 * m + rowsel) * FROW + T * 32 + koff);
#pragma unroll
            for (int nt = 0; nt < 2; nt++)
#pragma unroll
                for (int T = 0; T < 4; T++) {
                    mma16816(d[m][nt], ah[T], bh[nt][T][0], bh[nt][T][1]);
                    mma16816(d[m][nt], ah[T], bl[nt][T][0], bl[nt][T][1]);
                }
        }
    }

    // ---- epilogue: bias + log_softmax (4-lane groups per image) -------------
    const int q = lane & 3;
    const float b0 = bias_sh[2 * q], b1 = bias_sh[2 * q + 1];
    const float b8 = bias_sh[8], b9 = bias_sh[9];
#pragma unroll
    for (int m = 0; m < 2; m++)
#pragma unroll
        for (int h = 0; h < 2; h++) {
            int img = wimg + 16 * m + 8 * h + (lane >> 2);
            float v0 = d[m][0][2 * h] + b0;
            float v1 = d[m][0][2 * h + 1] + b1;
            float v2 = (q == 0) ? d[m][1][2 * h] + b8 : -1e30f;
            float v3 = (q == 0) ? d[m][1][2 * h + 1] + b9 : -1e30f;
            float mx = fmaxf(fmaxf(v0, v1), fmaxf(v2, v3));
            mx = fmaxf(mx, __shfl_xor_sync(0xffffffffu, mx, 1));
            mx = fmaxf(mx, __shfl_xor_sync(0xffffffffu, mx, 2));
            float s = __expf(v0 - mx) + __expf(v1 - mx);
            if (q == 0) s += __expf(v2 - mx) + __expf(v3 - mx);
            s += __shfl_xor_sync(0xffffffffu, s, 1);
            s += __shfl_xor_sync(0xffffffffu, s, 2);
            float lse = mx + __logf(s);
            if (img < batch) {
                float* op = out + (size_t)img * 10;
                *(float2*)(op + 2 * q) = make_float2(v0 - lse, v1 - lse);
                if (q == 0) *(float2*)(op + 8) = make_float2(v2 - lse, v3 - lse);
            }
        }
}

extern "C" void kernel_launch(void* const* d_in, const int* in_sizes, int n_in,
                              void* d_out, int out_size) {
    const float* x = (const float*)d_in[0];   // (B,1,28,28) fp32
    const float* W = (const float*)d_in[1];   // (10,784)    fp32
    const float* b = (const float*)d_in[2];   // (10,)       fp32
    float* out = (float*)d_out;               // (B,10)      fp32

    int batch = in_sizes[0] / 784;

    prep_w<<<(NCHUNK * 16 * 64 + 255) / 256, 256>>>(W);

    int grid = (batch + IMG_BLK - 1) / IMG_BLK;
    cudaFuncSetAttribute(quanv_hmma, cudaFuncAttributeMaxDynamicSharedMemorySize, SMEM_REQ);
    quanv_hmma<<<grid, THREADS, SMEM_REQ>>>(x, b, out, batch);
}